// round 13
// baseline (speedup 1.0000x reference)
#include <cuda_runtime.h>
#include <cuda_bf16.h>
#include <cstdint>

#define NB 32
#define NC 64
#define NPIX 16384
#define GSPLIT 8
#define GCH 32   // chunks per gram CTA: (16384/8)/64

__device__ float g_PQ[NB * GSPLIT * 128 * 64];              // split-K partials [p][m:128][d:64]
__device__ __align__(128) unsigned char g_Aimg[NB * 16384]; // per-batch A image: 64 rows x 256B ([Ah|Al]), row-swizzled

// ---------------------------------------------------------------------------
__device__ __forceinline__ uint32_t smem_u32(const void* p) {
    uint32_t a;
    asm("{ .reg .u64 t; cvta.to.shared.u64 t, %1; cvt.u32.u64 %0, t; }" : "=r"(a) : "l"(p));
    return a;
}
__device__ __forceinline__ void ldsm4(uint32_t& r0, uint32_t& r1, uint32_t& r2, uint32_t& r3, uint32_t a) {
    asm volatile("ldmatrix.sync.aligned.m8n8.x4.shared.b16 {%0,%1,%2,%3}, [%4];"
                 : "=r"(r0), "=r"(r1), "=r"(r2), "=r"(r3) : "r"(a));
}
__device__ __forceinline__ void ldsm4t(uint32_t& r0, uint32_t& r1, uint32_t& r2, uint32_t& r3, uint32_t a) {
    asm volatile("ldmatrix.sync.aligned.m8n8.x4.trans.shared.b16 {%0,%1,%2,%3}, [%4];"
                 : "=r"(r0), "=r"(r1), "=r"(r2), "=r"(r3) : "r"(a));
}
__device__ __forceinline__ void mma16816(float* d, uint32_t a0, uint32_t a1, uint32_t a2, uint32_t a3,
                                         uint32_t b0, uint32_t b1) {
    asm volatile("mma.sync.aligned.m16n8k16.row.col.f32.bf16.bf16.f32 "
                 "{%0,%1,%2,%3}, {%4,%5,%6,%7}, {%8,%9}, {%0,%1,%2,%3};"
                 : "+f"(d[0]), "+f"(d[1]), "+f"(d[2]), "+f"(d[3])
                 : "r"(a0), "r"(a1), "r"(a2), "r"(a3), "r"(b0), "r"(b1));
}

// row-swizzled offset within an image of RB-byte rows: XOR col bits[6:4] with (row&7)
__device__ __forceinline__ uint32_t offr(uint32_t row, uint32_t colb, uint32_t RB) {
    return row * RB + (colb ^ ((row & 7) << 4));
}

__device__ __forceinline__ void split_sts(uint32_t hi_addr, uint32_t lo_addr, float4 v) {
    __nv_bfloat16 h0 = __float2bfloat16(v.x), h1 = __float2bfloat16(v.y);
    __nv_bfloat16 h2 = __float2bfloat16(v.z), h3 = __float2bfloat16(v.w);
    float l0 = v.x - __bfloat162float(h0), l1 = v.y - __bfloat162float(h1);
    float l2 = v.z - __bfloat162float(h2), l3 = v.w - __bfloat162float(h3);
    uint32_t hw0 = (uint32_t)__bfloat16_as_ushort(h0) | ((uint32_t)__bfloat16_as_ushort(h1) << 16);
    uint32_t hw1 = (uint32_t)__bfloat16_as_ushort(h2) | ((uint32_t)__bfloat16_as_ushort(h3) << 16);
    __nv_bfloat16 g0 = __float2bfloat16(l0), g1 = __float2bfloat16(l1);
    __nv_bfloat16 g2 = __float2bfloat16(l2), g3 = __float2bfloat16(l3);
    uint32_t lw0 = (uint32_t)__bfloat16_as_ushort(g0) | ((uint32_t)__bfloat16_as_ushort(g1) << 16);
    uint32_t lw1 = (uint32_t)__bfloat16_as_ushort(g2) | ((uint32_t)__bfloat16_as_ushort(g3) << 16);
    asm volatile("st.shared.v2.b32 [%0], {%1,%2};" :: "r"(hi_addr), "r"(hw0), "r"(hw1) : "memory");
    asm volatile("st.shared.v2.b32 [%0], {%1,%2};" :: "r"(lo_addr), "r"(lw0), "r"(lw1) : "memory");
}

// ---------------------------------------------------------------------------
// Gram split-K, double-buffered 64-px chunks (1 barrier per chunk).
// Buffer: 128 rows x 128B bf16 (rows 0..63 = xh, 64..127 = xl), row-swizzled.
// Warp tile: M=32 (rows 32*(w&3)..), N=32 (d cols 32*(w>>2)..).
// launch_bounds(256,3): cap regs at 84 to fit 3 CTAs/SM (was 97 regs -> 2 CTAs).
__global__ void __launch_bounds__(256, 3) k_gram(const float* __restrict__ x) {
    __shared__ __align__(128) unsigned char img[2][16384];
    int b = blockIdx.y, s = blockIdx.x;
    int tid = threadIdx.x;
    int w = tid >> 5, lane = tid & 31;
    int lr = lane & 7, grp = lane >> 3;
    uint32_t base0 = smem_u32(img);

    const float* xb = x + (size_t)b * NC * NPIX + s * (NPIX / GSPLIT);
    int px4 = tid & 15;
    int r0  = tid >> 4;
    uint32_t hoff[4], loff[4];
    #pragma unroll
    for (int k = 0; k < 4; k++) {
        hoff[k] = offr(r0 + 16 * k,      px4 * 8, 128);
        loff[k] = offr(r0 + 16 * k + 64, px4 * 8, 128);
    }

    uint32_t xorv = (uint32_t)lr << 4;
    int mbase = 32 * (w & 3);
    int nbase = 32 * (w >> 2);
    uint32_t aRow[2], bRow[2];
    #pragma unroll
    for (int t2 = 0; t2 < 2; t2++) {
        aRow[t2] = (uint32_t)(mbase + 16 * t2 + lr + 8 * (grp & 1)) * 128;
        bRow[t2] = (uint32_t)(nbase + 16 * t2 + lr + 8 * (grp >> 1)) * 128;
    }
    uint32_t aCol = (uint32_t)(grp >> 1) * 16;   // + ks*32, then ^ xorv
    uint32_t bCol = (uint32_t)(grp & 1) * 16;

    float acc[2][2][2][4] = {};

    float4 rg[4];
    #pragma unroll
    for (int k = 0; k < 4; k++)
        rg[k] = *(const float4*)(xb + (size_t)(r0 + 16 * k) * NPIX + 4 * px4);

    for (int i = 0; i < GCH; i++) {
        uint32_t bufb = base0 + (uint32_t)(i & 1) * 16384;
        #pragma unroll
        for (int k = 0; k < 4; k++) split_sts(bufb + hoff[k], bufb + loff[k], rg[k]);
        __syncthreads();
        if (i + 1 < GCH) {
            const float* xc = xb + (i + 1) * 64;
            #pragma unroll
            for (int k = 0; k < 4; k++)
                rg[k] = *(const float4*)(xc + (size_t)(r0 + 16 * k) * NPIX + 4 * px4);
        }
        #pragma unroll
        for (int ks = 0; ks < 4; ks++) {
            uint32_t ac = (aCol + ks * 32) ^ xorv;
            uint32_t bc = (bCol + ks * 32) ^ xorv;
            uint32_t a[2][4], bb[2][4];
            #pragma unroll
            for (int t2 = 0; t2 < 2; t2++)
                ldsm4(a[t2][0], a[t2][1], a[t2][2], a[t2][3], bufb + aRow[t2] + ac);
            #pragma unroll
            for (int t2 = 0; t2 < 2; t2++)
                ldsm4(bb[t2][0], bb[t2][1], bb[t2][2], bb[t2][3], bufb + bRow[t2] + bc);
            #pragma unroll
            for (int am = 0; am < 2; am++)
                #pragma unroll
                for (int bn = 0; bn < 2; bn++) {
                    mma16816(acc[am][bn][0], a[am][0], a[am][1], a[am][2], a[am][3], bb[bn][0], bb[bn][1]);
                    mma16816(acc[am][bn][1], a[am][0], a[am][1], a[am][2], a[am][3], bb[bn][2], bb[bn][3]);
                }
        }
    }

    float* P = g_PQ + (size_t)(b * GSPLIT + s) * 8192;
    int lr2 = lane >> 2, lc2 = 2 * (lane & 3);
    #pragma unroll
    for (int am = 0; am < 2; am++)
        #pragma unroll
        for (int bn = 0; bn < 2; bn++)
            #pragma unroll
            for (int q = 0; q < 2; q++) {
                int m = mbase + 16 * am + lr2;
                int d = nbase + 16 * bn + 8 * q + lc2;
                float* a4 = acc[am][bn][q];
                *(float2*)(P + (size_t)m * 64 + d)       = make_float2(a4[0], a4[1]);
                *(float2*)(P + (size_t)(m + 8) * 64 + d) = make_float2(a4[2], a4[3]);
            }
}

// ---------------------------------------------------------------------------
// FUSED: sigma (power iteration) + split-K reduction + A_b = (gamma/sigma)*(G_b W) + I.
// G = hh + lh + lh^T summed over the 8 partials (read directly from g_PQ).
// Writes A image: 64 rows(c) x 256B: [Ah(e) | Al(e)] bf16, row-swizzled.
// grid = NB*2 (h = half of c rows).
__global__ void __launch_bounds__(256) k_matA(const float* __restrict__ W,
                                              const float* __restrict__ gamma,
                                              const float* __restrict__ u) {
    __shared__ float Bs[64][65];
    __shared__ float Ws[64][65];
    __shared__ float vv[64];
    __shared__ float red[64];
    __shared__ float sscale;
    int b = blockIdx.x >> 1, h = blockIdx.x & 1;
    int tid = threadIdx.x;
    const float* P = g_PQ + (size_t)b * GSPLIT * 8192;

    #pragma unroll
    for (int q = 0; q < 4; q++) {
        int f = tid + 256 * q;
        float4 a = ((const float4*)(P + 4096))[f];
        #pragma unroll
        for (int s2 = 1; s2 < GSPLIT; s2++) {
            float4 t2 = ((const float4*)(P + (size_t)s2 * 8192 + 4096))[f];
            a.x += t2.x; a.y += t2.y; a.z += t2.z; a.w += t2.w;
        }
        int row = f >> 4, col = (f & 15) * 4;
        Bs[row][col] = a.x; Bs[row][col + 1] = a.y; Bs[row][col + 2] = a.z; Bs[row][col + 3] = a.w;
        float4 wv = ((const float4*)W)[f];
        Ws[row][col] = wv.x; Ws[row][col + 1] = wv.y; Ws[row][col + 2] = wv.z; Ws[row][col + 3] = wv.w;
    }
    __syncthreads();

    // ---- sigma: v = l2norm(W^T u); sigma = ||W v|| ----
    if (tid < 64) {
        float s = 0.f;
        for (int c = 0; c < 64; c++) s = fmaf(Ws[c][tid], u[c], s);
        vv[tid] = s;
        red[tid] = s * s;
    }
    __syncthreads();
    for (int off = 32; off > 0; off >>= 1) {
        if (tid < off) red[tid] += red[tid + off];
        __syncthreads();
    }
    float nv = fmaxf(sqrtf(red[0]), 1e-12f);
    __syncthreads();
    if (tid < 64) {
        float s = 0.f;
        for (int c = 0; c < 64; c++) s = fmaf(Ws[tid][c], vv[c], s);
        s /= nv;
        red[tid] = s * s;
    }
    __syncthreads();
    for (int off = 32; off > 0; off >>= 1) {
        if (tid < off) red[tid] += red[tid + off];
        __syncthreads();
    }
    if (tid == 0) sscale = gamma[0] / fmaxf(sqrtf(red[0]), 1e-12f);

    // ---- G rows for this CTA's 32 c's: hh (summed from gmem) + lh + lh^T ----
    int c  = 32 * h + (tid >> 3);
    int e0 = (tid & 7) * 8;
    float g[8];
    {
        float4 A0 = ((const float4*)(P + c * 64 + e0))[0];
        float4 A1 = ((const float4*)(P + c * 64 + e0))[1];
        #pragma unroll
        for (int s2 = 1; s2 < GSPLIT; s2++) {
            float4 t0 = ((const float4*)(P + (size_t)s2 * 8192 + c * 64 + e0))[0];
            float4 t1 = ((const float4*)(P + (size_t)s2 * 8192 + c * 64 + e0))[1];
            A0.x += t0.x; A0.y += t0.y; A0.z += t0.z; A0.w += t0.w;
            A1.x += t1.x; A1.y += t1.y; A1.z += t1.z; A1.w += t1.w;
        }
        g[0] = A0.x; g[1] = A0.y; g[2] = A0.z; g[3] = A0.w;
        g[4] = A1.x; g[5] = A1.y; g[6] = A1.z; g[7] = A1.w;
        #pragma unroll
        for (int j = 0; j < 8; j++) g[j] += Bs[c][e0 + j] + Bs[e0 + j][c];
    }
    __syncthreads();
    #pragma unroll
    for (int j = 0; j < 8; j++) Bs[c][e0 + j] = g[j];
    __syncthreads();

    // ---- A = sc*(G W) + I, bf16 hi/lo split, swizzled image ----
    float acc[8] = {};
    #pragma unroll 8
    for (int d = 0; d < 64; d++) {
        float a = Bs[c][d];
        #pragma unroll
        for (int j = 0; j < 8; j++) acc[j] = fmaf(a, Ws[d][e0 + j], acc[j]);
    }
    float sc = sscale;
    uint32_t hw[4], lw[4];
    #pragma unroll
    for (int j = 0; j < 4; j++) {
        float v0 = fmaf(sc, acc[2 * j],     (c == e0 + 2 * j)     ? 1.f : 0.f);
        float v1 = fmaf(sc, acc[2 * j + 1], (c == e0 + 2 * j + 1) ? 1.f : 0.f);
        __nv_bfloat16 h0 = __float2bfloat16(v0), h1 = __float2bfloat16(v1);
        float l0 = v0 - __bfloat162float(h0), l1 = v1 - __bfloat162float(h1);
        __nv_bfloat16 g0 = __float2bfloat16(l0), g1 = __float2bfloat16(l1);
        hw[j] = (uint32_t)__bfloat16_as_ushort(h0) | ((uint32_t)__bfloat16_as_ushort(h1) << 16);
        lw[j] = (uint32_t)__bfloat16_as_ushort(g0) | ((uint32_t)__bfloat16_as_ushort(g1) << 16);
    }
    unsigned char* Ai = g_Aimg + (size_t)b * 16384;
    *(uint4*)(Ai + offr(c, e0 * 2, 256))       = make_uint4(hw[0], hw[1], hw[2], hw[3]);
    *(uint4*)(Ai + offr(c, 128 + e0 * 2, 256)) = make_uint4(lw[0], lw[1], lw[2], lw[3]);
}

// ---------------------------------------------------------------------------
// out tile (128 px): warp tile M=64 (all c), N=16 (px 16*w..16*w+15).
// Quarter-products kept: Ah*xh, Al*xh (j 0..7 @ p=0), Ah*xl (j 0..3 @ p=1).
// Al*xl (~2^-32 relative) dropped: 25% fewer mma/ldsm.
__global__ void __launch_bounds__(256, 3) k_out(const float* __restrict__ x,
                                                float* __restrict__ out) {
    __shared__ __align__(128) unsigned char As[16384];   // 64 rows x 256B
    __shared__ __align__(128) unsigned char Bsi[32768];  // 128 rows ([xh;xl]) x 256B
    int b = blockIdx.y, n0 = blockIdx.x * 128;
    int tid = threadIdx.x;
    int w = tid >> 5, lane = tid & 31;
    int lr = lane & 7, grp = lane >> 3;
    uint32_t asb = smem_u32(As), bsb = smem_u32(Bsi);

    const uint4* Ag = (const uint4*)(g_Aimg + (size_t)b * 16384);
    #pragma unroll
    for (int q = 0; q < 4; q++) ((uint4*)As)[tid + 256 * q] = Ag[tid + 256 * q];

    const float* xb = x + (size_t)b * NC * NPIX + n0;
    int r0 = tid >> 5;
    #pragma unroll
    for (int k = 0; k < 8; k++) {
        int e = r0 + 8 * k;
        float4 v = *(const float4*)(xb + (size_t)e * NPIX + 4 * lane);
        split_sts(bsb + offr(e, lane * 8, 256), bsb + offr(e + 64, lane * 8, 256), v);
    }
    __syncthreads();

    uint32_t xorv = (uint32_t)lr << 4;
    uint32_t aRow[4];
    #pragma unroll
    for (int mt = 0; mt < 4; mt++)
        aRow[mt] = asb + (uint32_t)(16 * mt + lr + 8 * (grp & 1)) * 256;
    uint32_t aColB = (uint32_t)(grp >> 1) * 16;             // + j*32, ^ xorv
    uint32_t bColX = ((uint32_t)(32 * w) + (uint32_t)(grp >> 1) * 16) ^ xorv;
    uint32_t bRowL = (uint32_t)(lr + 8 * (grp & 1));

    float acc[4][2][4] = {};
    #pragma unroll
    for (int j = 0; j < 8; j++) {
        uint32_t ac = (aColB + j * 32) ^ xorv;
        uint32_t a[4][4];
        #pragma unroll
        for (int mt = 0; mt < 4; mt++)
            ldsm4(a[mt][0], a[mt][1], a[mt][2], a[mt][3], aRow[mt] + ac);
        #pragma unroll
        for (int p = 0; p < 2; p++) {
            if (p == 1 && j >= 4) continue;   // skip Al*xl quarter-product
            uint32_t brow = (uint32_t)((j & 3) * 16 + p * 64) + bRowL;
            uint32_t b0, b1, b2, b3;
            ldsm4t(b0, b1, b2, b3, bsb + brow * 256 + bColX);
            #pragma unroll
            for (int mt = 0; mt < 4; mt++) {
                mma16816(acc[mt][0], a[mt][0], a[mt][1], a[mt][2], a[mt][3], b0, b1);
                mma16816(acc[mt][1], a[mt][0], a[mt][1], a[mt][2], a[mt][3], b2, b3);
            }
        }
    }

    float* ob = out + (size_t)b * NC * NPIX + n0;
    int pc = 16 * w + 2 * (lane & 3);
    int lr2 = lane >> 2;
    #pragma unroll
    for (int mt = 0; mt < 4; mt++) {
        int c = 16 * mt + lr2;
        #pragma unroll
        for (int q = 0; q < 2; q++) {
            *(float2*)(ob + (size_t)c * NPIX + pc + 8 * q)       = make_float2(acc[mt][q][0], acc[mt][q][1]);
            *(float2*)(ob + (size_t)(c + 8) * NPIX + pc + 8 * q) = make_float2(acc[mt][q][2], acc[mt][q][3]);
        }
    }
}

// ---------------------------------------------------------------------------
extern "C" void kernel_launch(void* const* d_in, const int* in_sizes, int n_in,
                              void* d_out, int out_size) {
    const float* x     = (const float*)d_in[0];
    const float* W     = (const float*)d_in[1];
    const float* gamma = (const float*)d_in[2];
    const float* u     = (const float*)d_in[3];
    float* out = (float*)d_out;

    k_gram<<<dim3(GSPLIT, NB), 256>>>(x);
    k_matA<<<NB * 2, 256>>>(W, gamma, u);
    k_out<<<dim3(NPIX / 128, NB), 256>>>(x, out);
}

// round 15
// speedup vs baseline: 1.2376x; 1.2376x over previous
#include <cuda_runtime.h>
#include <cuda_bf16.h>
#include <cstdint>

#define NB 32
#define NC 64
#define NPIX 16384
#define GSPLIT 8
#define GCH 32   // chunks per gram CTA: (16384/8)/64

__device__ float g_PQ[NB * GSPLIT * 128 * 64];              // split-K partials [p][m:128][d:64]
__device__ __align__(128) unsigned char g_Aimg[NB * 16384]; // per-batch A image: 64 rows x 256B ([Ah|Al]), row-swizzled

// ---------------------------------------------------------------------------
__device__ __forceinline__ uint32_t smem_u32(const void* p) {
    uint32_t a;
    asm("{ .reg .u64 t; cvta.to.shared.u64 t, %1; cvt.u32.u64 %0, t; }" : "=r"(a) : "l"(p));
    return a;
}
__device__ __forceinline__ void ldsm4(uint32_t& r0, uint32_t& r1, uint32_t& r2, uint32_t& r3, uint32_t a) {
    asm volatile("ldmatrix.sync.aligned.m8n8.x4.shared.b16 {%0,%1,%2,%3}, [%4];"
                 : "=r"(r0), "=r"(r1), "=r"(r2), "=r"(r3) : "r"(a));
}
__device__ __forceinline__ void ldsm4t(uint32_t& r0, uint32_t& r1, uint32_t& r2, uint32_t& r3, uint32_t a) {
    asm volatile("ldmatrix.sync.aligned.m8n8.x4.trans.shared.b16 {%0,%1,%2,%3}, [%4];"
                 : "=r"(r0), "=r"(r1), "=r"(r2), "=r"(r3) : "r"(a));
}
__device__ __forceinline__ void mma16816(float* d, uint32_t a0, uint32_t a1, uint32_t a2, uint32_t a3,
                                         uint32_t b0, uint32_t b1) {
    asm volatile("mma.sync.aligned.m16n8k16.row.col.f32.bf16.bf16.f32 "
                 "{%0,%1,%2,%3}, {%4,%5,%6,%7}, {%8,%9}, {%0,%1,%2,%3};"
                 : "+f"(d[0]), "+f"(d[1]), "+f"(d[2]), "+f"(d[3])
                 : "r"(a0), "r"(a1), "r"(a2), "r"(a3), "r"(b0), "r"(b1));
}

// row-swizzled offset within an image of RB-byte rows: XOR col bits[6:4] with (row&7)
__device__ __forceinline__ uint32_t offr(uint32_t row, uint32_t colb, uint32_t RB) {
    return row * RB + (colb ^ ((row & 7) << 4));
}

__device__ __forceinline__ void split_sts(uint32_t hi_addr, uint32_t lo_addr, float4 v) {
    __nv_bfloat16 h0 = __float2bfloat16(v.x), h1 = __float2bfloat16(v.y);
    __nv_bfloat16 h2 = __float2bfloat16(v.z), h3 = __float2bfloat16(v.w);
    float l0 = v.x - __bfloat162float(h0), l1 = v.y - __bfloat162float(h1);
    float l2 = v.z - __bfloat162float(h2), l3 = v.w - __bfloat162float(h3);
    uint32_t hw0 = (uint32_t)__bfloat16_as_ushort(h0) | ((uint32_t)__bfloat16_as_ushort(h1) << 16);
    uint32_t hw1 = (uint32_t)__bfloat16_as_ushort(h2) | ((uint32_t)__bfloat16_as_ushort(h3) << 16);
    __nv_bfloat16 g0 = __float2bfloat16(l0), g1 = __float2bfloat16(l1);
    __nv_bfloat16 g2 = __float2bfloat16(l2), g3 = __float2bfloat16(l3);
    uint32_t lw0 = (uint32_t)__bfloat16_as_ushort(g0) | ((uint32_t)__bfloat16_as_ushort(g1) << 16);
    uint32_t lw1 = (uint32_t)__bfloat16_as_ushort(g2) | ((uint32_t)__bfloat16_as_ushort(g3) << 16);
    asm volatile("st.shared.v2.b32 [%0], {%1,%2};" :: "r"(hi_addr), "r"(hw0), "r"(hw1) : "memory");
    asm volatile("st.shared.v2.b32 [%0], {%1,%2};" :: "r"(lo_addr), "r"(lw0), "r"(lw1) : "memory");
}

// ---------------------------------------------------------------------------
// Gram split-K, double-buffered 64-px chunks (1 barrier per chunk) — R12 config
// (no launch_bounds occupancy clamp; 97 regs / 2 CTAs measured 39.7us).
// Buffer: 128 rows x 128B bf16 (rows 0..63 = xh, 64..127 = xl), row-swizzled.
// Warp tile: M=32 (rows 32*(w&3)..), N=32 (d cols 32*(w>>2)..).
__global__ void __launch_bounds__(256) k_gram(const float* __restrict__ x) {
    __shared__ __align__(128) unsigned char img[2][16384];
    int b = blockIdx.y, s = blockIdx.x;
    int tid = threadIdx.x;
    int w = tid >> 5, lane = tid & 31;
    int lr = lane & 7, grp = lane >> 3;
    uint32_t base0 = smem_u32(img);

    const float* xb = x + (size_t)b * NC * NPIX + s * (NPIX / GSPLIT);
    int px4 = tid & 15;
    int r0  = tid >> 4;
    uint32_t hoff[4], loff[4];
    #pragma unroll
    for (int k = 0; k < 4; k++) {
        hoff[k] = offr(r0 + 16 * k,      px4 * 8, 128);
        loff[k] = offr(r0 + 16 * k + 64, px4 * 8, 128);
    }

    uint32_t xorv = (uint32_t)lr << 4;
    int mbase = 32 * (w & 3);
    int nbase = 32 * (w >> 2);
    uint32_t aRow[2], bRow[2];
    #pragma unroll
    for (int t2 = 0; t2 < 2; t2++) {
        aRow[t2] = (uint32_t)(mbase + 16 * t2 + lr + 8 * (grp & 1)) * 128;
        bRow[t2] = (uint32_t)(nbase + 16 * t2 + lr + 8 * (grp >> 1)) * 128;
    }
    uint32_t aCol = (uint32_t)(grp >> 1) * 16;   // + ks*32, then ^ xorv
    uint32_t bCol = (uint32_t)(grp & 1) * 16;

    float acc[2][2][2][4] = {};

    float4 rg[4];
    #pragma unroll
    for (int k = 0; k < 4; k++)
        rg[k] = *(const float4*)(xb + (size_t)(r0 + 16 * k) * NPIX + 4 * px4);

    for (int i = 0; i < GCH; i++) {
        uint32_t bufb = base0 + (uint32_t)(i & 1) * 16384;
        #pragma unroll
        for (int k = 0; k < 4; k++) split_sts(bufb + hoff[k], bufb + loff[k], rg[k]);
        __syncthreads();
        if (i + 1 < GCH) {
            const float* xc = xb + (i + 1) * 64;
            #pragma unroll
            for (int k = 0; k < 4; k++)
                rg[k] = *(const float4*)(xc + (size_t)(r0 + 16 * k) * NPIX + 4 * px4);
        }
        #pragma unroll
        for (int ks = 0; ks < 4; ks++) {
            uint32_t ac = (aCol + ks * 32) ^ xorv;
            uint32_t bc = (bCol + ks * 32) ^ xorv;
            uint32_t a[2][4], bb[2][4];
            #pragma unroll
            for (int t2 = 0; t2 < 2; t2++)
                ldsm4(a[t2][0], a[t2][1], a[t2][2], a[t2][3], bufb + aRow[t2] + ac);
            #pragma unroll
            for (int t2 = 0; t2 < 2; t2++)
                ldsm4(bb[t2][0], bb[t2][1], bb[t2][2], bb[t2][3], bufb + bRow[t2] + bc);
            #pragma unroll
            for (int am = 0; am < 2; am++)
                #pragma unroll
                for (int bn = 0; bn < 2; bn++) {
                    mma16816(acc[am][bn][0], a[am][0], a[am][1], a[am][2], a[am][3], bb[bn][0], bb[bn][1]);
                    mma16816(acc[am][bn][1], a[am][0], a[am][1], a[am][2], a[am][3], bb[bn][2], bb[bn][3]);
                }
        }
    }

    float* P = g_PQ + (size_t)(b * GSPLIT + s) * 8192;
    int lr2 = lane >> 2, lc2 = 2 * (lane & 3);
    #pragma unroll
    for (int am = 0; am < 2; am++)
        #pragma unroll
        for (int bn = 0; bn < 2; bn++)
            #pragma unroll
            for (int q = 0; q < 2; q++) {
                int m = mbase + 16 * am + lr2;
                int d = nbase + 16 * bn + 8 * q + lc2;
                float* a4 = acc[am][bn][q];
                *(float2*)(P + (size_t)m * 64 + d)       = make_float2(a4[0], a4[1]);
                *(float2*)(P + (size_t)(m + 8) * 64 + d) = make_float2(a4[2], a4[3]);
            }
}

// ---------------------------------------------------------------------------
// FUSED: sigma (power iteration) + split-K reduction + A_b = (gamma/sigma)*(G_b W) + I.
// G = hh + lh + lh^T summed over the 8 partials (read directly from g_PQ).
// Writes A image: 64 rows(c) x 256B: [Ah(e) | Al(e)] bf16, row-swizzled.
// grid = NB*2 (h = half of c rows).
__global__ void __launch_bounds__(256) k_matA(const float* __restrict__ W,
                                              const float* __restrict__ gamma,
                                              const float* __restrict__ u) {
    __shared__ float Bs[64][65];
    __shared__ float Ws[64][65];
    __shared__ float vv[64];
    __shared__ float red[64];
    __shared__ float sscale;
    int b = blockIdx.x >> 1, h = blockIdx.x & 1;
    int tid = threadIdx.x;
    const float* P = g_PQ + (size_t)b * GSPLIT * 8192;

    #pragma unroll
    for (int q = 0; q < 4; q++) {
        int f = tid + 256 * q;
        float4 a = ((const float4*)(P + 4096))[f];
        #pragma unroll
        for (int s2 = 1; s2 < GSPLIT; s2++) {
            float4 t2 = ((const float4*)(P + (size_t)s2 * 8192 + 4096))[f];
            a.x += t2.x; a.y += t2.y; a.z += t2.z; a.w += t2.w;
        }
        int row = f >> 4, col = (f & 15) * 4;
        Bs[row][col] = a.x; Bs[row][col + 1] = a.y; Bs[row][col + 2] = a.z; Bs[row][col + 3] = a.w;
        float4 wv = ((const float4*)W)[f];
        Ws[row][col] = wv.x; Ws[row][col + 1] = wv.y; Ws[row][col + 2] = wv.z; Ws[row][col + 3] = wv.w;
    }
    __syncthreads();

    // ---- sigma: v = l2norm(W^T u); sigma = ||W v|| ----
    if (tid < 64) {
        float s = 0.f;
        for (int c = 0; c < 64; c++) s = fmaf(Ws[c][tid], u[c], s);
        vv[tid] = s;
        red[tid] = s * s;
    }
    __syncthreads();
    for (int off = 32; off > 0; off >>= 1) {
        if (tid < off) red[tid] += red[tid + off];
        __syncthreads();
    }
    float nv = fmaxf(sqrtf(red[0]), 1e-12f);
    __syncthreads();
    if (tid < 64) {
        float s = 0.f;
        for (int c = 0; c < 64; c++) s = fmaf(Ws[tid][c], vv[c], s);
        s /= nv;
        red[tid] = s * s;
    }
    __syncthreads();
    for (int off = 32; off > 0; off >>= 1) {
        if (tid < off) red[tid] += red[tid + off];
        __syncthreads();
    }
    if (tid == 0) sscale = gamma[0] / fmaxf(sqrtf(red[0]), 1e-12f);

    // ---- G rows for this CTA's 32 c's: hh (summed from gmem) + lh + lh^T ----
    int c  = 32 * h + (tid >> 3);
    int e0 = (tid & 7) * 8;
    float g[8];
    {
        float4 A0 = ((const float4*)(P + c * 64 + e0))[0];
        float4 A1 = ((const float4*)(P + c * 64 + e0))[1];
        #pragma unroll
        for (int s2 = 1; s2 < GSPLIT; s2++) {
            float4 t0 = ((const float4*)(P + (size_t)s2 * 8192 + c * 64 + e0))[0];
            float4 t1 = ((const float4*)(P + (size_t)s2 * 8192 + c * 64 + e0))[1];
            A0.x += t0.x; A0.y += t0.y; A0.z += t0.z; A0.w += t0.w;
            A1.x += t1.x; A1.y += t1.y; A1.z += t1.z; A1.w += t1.w;
        }
        g[0] = A0.x; g[1] = A0.y; g[2] = A0.z; g[3] = A0.w;
        g[4] = A1.x; g[5] = A1.y; g[6] = A1.z; g[7] = A1.w;
        #pragma unroll
        for (int j = 0; j < 8; j++) g[j] += Bs[c][e0 + j] + Bs[e0 + j][c];
    }
    __syncthreads();
    #pragma unroll
    for (int j = 0; j < 8; j++) Bs[c][e0 + j] = g[j];
    __syncthreads();

    // ---- A = sc*(G W) + I, bf16 hi/lo split, swizzled image ----
    float acc[8] = {};
    #pragma unroll 8
    for (int d = 0; d < 64; d++) {
        float a = Bs[c][d];
        #pragma unroll
        for (int j = 0; j < 8; j++) acc[j] = fmaf(a, Ws[d][e0 + j], acc[j]);
    }
    float sc = sscale;
    uint32_t hw[4], lw[4];
    #pragma unroll
    for (int j = 0; j < 4; j++) {
        float v0 = fmaf(sc, acc[2 * j],     (c == e0 + 2 * j)     ? 1.f : 0.f);
        float v1 = fmaf(sc, acc[2 * j + 1], (c == e0 + 2 * j + 1) ? 1.f : 0.f);
        __nv_bfloat16 h0 = __float2bfloat16(v0), h1 = __float2bfloat16(v1);
        float l0 = v0 - __bfloat162float(h0), l1 = v1 - __bfloat162float(h1);
        __nv_bfloat16 g0 = __float2bfloat16(l0), g1 = __float2bfloat16(l1);
        hw[j] = (uint32_t)__bfloat16_as_ushort(h0) | ((uint32_t)__bfloat16_as_ushort(h1) << 16);
        lw[j] = (uint32_t)__bfloat16_as_ushort(g0) | ((uint32_t)__bfloat16_as_ushort(g1) << 16);
    }
    unsigned char* Ai = g_Aimg + (size_t)b * 16384;
    *(uint4*)(Ai + offr(c, e0 * 2, 256))       = make_uint4(hw[0], hw[1], hw[2], hw[3]);
    *(uint4*)(Ai + offr(c, 128 + e0 * 2, 256)) = make_uint4(lw[0], lw[1], lw[2], lw[3]);
}

// ---------------------------------------------------------------------------
// out tile (128 px): warp tile M=64 (all c), N=16 (px 16*w..16*w+15).
// Quarter-products kept: Ah*xh, Al*xh (j 0..7 @ p=0), Ah*xl (j 0..3 @ p=1).
// Al*xl (~2^-32 relative) dropped: 25% fewer mma/ldsm.
__global__ void __launch_bounds__(256, 3) k_out(const float* __restrict__ x,
                                                float* __restrict__ out) {
    __shared__ __align__(128) unsigned char As[16384];   // 64 rows x 256B
    __shared__ __align__(128) unsigned char Bsi[32768];  // 128 rows ([xh;xl]) x 256B
    int b = blockIdx.y, n0 = blockIdx.x * 128;
    int tid = threadIdx.x;
    int w = tid >> 5, lane = tid & 31;
    int lr = lane & 7, grp = lane >> 3;
    uint32_t asb = smem_u32(As), bsb = smem_u32(Bsi);

    const uint4* Ag = (const uint4*)(g_Aimg + (size_t)b * 16384);
    #pragma unroll
    for (int q = 0; q < 4; q++) ((uint4*)As)[tid + 256 * q] = Ag[tid + 256 * q];

    const float* xb = x + (size_t)b * NC * NPIX + n0;
    int r0 = tid >> 5;
    #pragma unroll
    for (int k = 0; k < 8; k++) {
        int e = r0 + 8 * k;
        float4 v = *(const float4*)(xb + (size_t)e * NPIX + 4 * lane);
        split_sts(bsb + offr(e, lane * 8, 256), bsb + offr(e + 64, lane * 8, 256), v);
    }
    __syncthreads();

    uint32_t xorv = (uint32_t)lr << 4;
    uint32_t aRow[4];
    #pragma unroll
    for (int mt = 0; mt < 4; mt++)
        aRow[mt] = asb + (uint32_t)(16 * mt + lr + 8 * (grp & 1)) * 256;
    uint32_t aColB = (uint32_t)(grp >> 1) * 16;             // + j*32, ^ xorv
    uint32_t bColX = ((uint32_t)(32 * w) + (uint32_t)(grp >> 1) * 16) ^ xorv;
    uint32_t bRowL = (uint32_t)(lr + 8 * (grp & 1));

    float acc[4][2][4] = {};
    #pragma unroll
    for (int j = 0; j < 8; j++) {
        uint32_t ac = (aColB + j * 32) ^ xorv;
        uint32_t a[4][4];
        #pragma unroll
        for (int mt = 0; mt < 4; mt++)
            ldsm4(a[mt][0], a[mt][1], a[mt][2], a[mt][3], aRow[mt] + ac);
        #pragma unroll
        for (int p = 0; p < 2; p++) {
            if (p == 1 && j >= 4) continue;   // skip Al*xl quarter-product
            uint32_t brow = (uint32_t)((j & 3) * 16 + p * 64) + bRowL;
            uint32_t b0, b1, b2, b3;
            ldsm4t(b0, b1, b2, b3, bsb + brow * 256 + bColX);
            #pragma unroll
            for (int mt = 0; mt < 4; mt++) {
                mma16816(acc[mt][0], a[mt][0], a[mt][1], a[mt][2], a[mt][3], b0, b1);
                mma16816(acc[mt][1], a[mt][0], a[mt][1], a[mt][2], a[mt][3], b2, b3);
            }
        }
    }

    float* ob = out + (size_t)b * NC * NPIX + n0;
    int pc = 16 * w + 2 * (lane & 3);
    int lr2 = lane >> 2;
    #pragma unroll
    for (int mt = 0; mt < 4; mt++) {
        int c = 16 * mt + lr2;
        #pragma unroll
        for (int q = 0; q < 2; q++) {
            *(float2*)(ob + (size_t)c * NPIX + pc + 8 * q)       = make_float2(acc[mt][q][0], acc[mt][q][1]);
            *(float2*)(ob + (size_t)(c + 8) * NPIX + pc + 8 * q) = make_float2(acc[mt][q][2], acc[mt][q][3]);
        }
    }
}

// ---------------------------------------------------------------------------
extern "C" void kernel_launch(void* const* d_in, const int* in_sizes, int n_in,
                              void* d_out, int out_size) {
    const float* x     = (const float*)d_in[0];
    const float* W     = (const float*)d_in[1];
    const float* gamma = (const float*)d_in[2];
    const float* u     = (const float*)d_in[3];
    float* out = (float*)d_out;

    k_gram<<<dim3(GSPLIT, NB), 256>>>(x);
    k_matA<<<NB * 2, 256>>>(W, gamma, u);
    k_out<<<dim3(NPIX / 128, NB), 256>>>(x, out);
}

// round 16
// speedup vs baseline: 1.2426x; 1.0040x over previous
#include <cuda_runtime.h>
#include <cuda_bf16.h>
#include <cstdint>

#define NB 32
#define NC 64
#define NPIX 16384
#define GSPLIT 8
#define GCH 32   // chunks per gram CTA: (16384/8)/64

__device__ float g_PQ[NB * GSPLIT * 128 * 64];              // split-K partials [p][m:128][d:64]
__device__ __align__(128) unsigned char g_Aimg[NB * 16384]; // per-batch A image: 64 rows x 256B ([Ah|Al]), row-swizzled

// ---------------------------------------------------------------------------
__device__ __forceinline__ uint32_t smem_u32(const void* p) {
    uint32_t a;
    asm("{ .reg .u64 t; cvta.to.shared.u64 t, %1; cvt.u32.u64 %0, t; }" : "=r"(a) : "l"(p));
    return a;
}
__device__ __forceinline__ void ldsm4(uint32_t& r0, uint32_t& r1, uint32_t& r2, uint32_t& r3, uint32_t a) {
    asm volatile("ldmatrix.sync.aligned.m8n8.x4.shared.b16 {%0,%1,%2,%3}, [%4];"
                 : "=r"(r0), "=r"(r1), "=r"(r2), "=r"(r3) : "r"(a));
}
__device__ __forceinline__ void ldsm4t(uint32_t& r0, uint32_t& r1, uint32_t& r2, uint32_t& r3, uint32_t a) {
    asm volatile("ldmatrix.sync.aligned.m8n8.x4.trans.shared.b16 {%0,%1,%2,%3}, [%4];"
                 : "=r"(r0), "=r"(r1), "=r"(r2), "=r"(r3) : "r"(a));
}
__device__ __forceinline__ void mma16816(float* d, uint32_t a0, uint32_t a1, uint32_t a2, uint32_t a3,
                                         uint32_t b0, uint32_t b1) {
    asm volatile("mma.sync.aligned.m16n8k16.row.col.f32.bf16.bf16.f32 "
                 "{%0,%1,%2,%3}, {%4,%5,%6,%7}, {%8,%9}, {%0,%1,%2,%3};"
                 : "+f"(d[0]), "+f"(d[1]), "+f"(d[2]), "+f"(d[3])
                 : "r"(a0), "r"(a1), "r"(a2), "r"(a3), "r"(b0), "r"(b1));
}

// row-swizzled offset within an image of RB-byte rows: XOR col bits[6:4] with (row&7)
__device__ __forceinline__ uint32_t offr(uint32_t row, uint32_t colb, uint32_t RB) {
    return row * RB + (colb ^ ((row & 7) << 4));
}

__device__ __forceinline__ void split_sts(uint32_t hi_addr, uint32_t lo_addr, float4 v) {
    __nv_bfloat16 h0 = __float2bfloat16(v.x), h1 = __float2bfloat16(v.y);
    __nv_bfloat16 h2 = __float2bfloat16(v.z), h3 = __float2bfloat16(v.w);
    float l0 = v.x - __bfloat162float(h0), l1 = v.y - __bfloat162float(h1);
    float l2 = v.z - __bfloat162float(h2), l3 = v.w - __bfloat162float(h3);
    uint32_t hw0 = (uint32_t)__bfloat16_as_ushort(h0) | ((uint32_t)__bfloat16_as_ushort(h1) << 16);
    uint32_t hw1 = (uint32_t)__bfloat16_as_ushort(h2) | ((uint32_t)__bfloat16_as_ushort(h3) << 16);
    __nv_bfloat16 g0 = __float2bfloat16(l0), g1 = __float2bfloat16(l1);
    __nv_bfloat16 g2 = __float2bfloat16(l2), g3 = __float2bfloat16(l3);
    uint32_t lw0 = (uint32_t)__bfloat16_as_ushort(g0) | ((uint32_t)__bfloat16_as_ushort(g1) << 16);
    uint32_t lw1 = (uint32_t)__bfloat16_as_ushort(g2) | ((uint32_t)__bfloat16_as_ushort(g3) << 16);
    asm volatile("st.shared.v2.b32 [%0], {%1,%2};" :: "r"(hi_addr), "r"(hw0), "r"(hw1) : "memory");
    asm volatile("st.shared.v2.b32 [%0], {%1,%2};" :: "r"(lo_addr), "r"(lw0), "r"(lw1) : "memory");
}

// ---------------------------------------------------------------------------
// Gram split-K, double-buffered 64-px chunks, 2-chunk register prefetch.
// Buffer: 128 rows x 128B bf16 (rows 0..63 = xh, 64..127 = xl), row-swizzled.
// Warp tile: M=32 (rows 32*(w&3)..), N=32 (d cols 32*(w>>2)..).
// 2-deep lookahead doubles in-flight DRAM bytes (16KB -> 32KB/CTA) to lift
// the MLP-limited ~3.5TB/s toward DRAM peak. (256,2) pins 2 CTAs/SM (<=128 regs).
__global__ void __launch_bounds__(256, 2) k_gram(const float* __restrict__ x) {
    __shared__ __align__(128) unsigned char img[2][16384];
    int b = blockIdx.y, s = blockIdx.x;
    int tid = threadIdx.x;
    int w = tid >> 5, lane = tid & 31;
    int lr = lane & 7, grp = lane >> 3;
    uint32_t base0 = smem_u32(img);

    const float* xb = x + (size_t)b * NC * NPIX + s * (NPIX / GSPLIT);
    int px4 = tid & 15;
    int r0  = tid >> 4;
    uint32_t hoff[4], loff[4];
    #pragma unroll
    for (int k = 0; k < 4; k++) {
        hoff[k] = offr(r0 + 16 * k,      px4 * 8, 128);
        loff[k] = offr(r0 + 16 * k + 64, px4 * 8, 128);
    }

    uint32_t xorv = (uint32_t)lr << 4;
    int mbase = 32 * (w & 3);
    int nbase = 32 * (w >> 2);
    uint32_t aRow[2], bRow[2];
    #pragma unroll
    for (int t2 = 0; t2 < 2; t2++) {
        aRow[t2] = (uint32_t)(mbase + 16 * t2 + lr + 8 * (grp & 1)) * 128;
        bRow[t2] = (uint32_t)(nbase + 16 * t2 + lr + 8 * (grp >> 1)) * 128;
    }
    uint32_t aCol = (uint32_t)(grp >> 1) * 16;   // + ks*32, then ^ xorv
    uint32_t bCol = (uint32_t)(grp & 1) * 16;

    float acc[2][2][2][4] = {};

    // 2-chunk register prefetch: rg[0] holds even chunks, rg[1] odd chunks.
    float4 rg[2][4];
    #pragma unroll
    for (int hf = 0; hf < 2; hf++)
        #pragma unroll
        for (int k = 0; k < 4; k++)
            rg[hf][k] = *(const float4*)(xb + (size_t)(r0 + 16 * k) * NPIX + hf * 64 + 4 * px4);

    for (int i = 0; i < GCH; i += 2) {
        #pragma unroll
        for (int hf = 0; hf < 2; hf++) {
            uint32_t bufb = base0 + (uint32_t)hf * 16384;
            #pragma unroll
            for (int k = 0; k < 4; k++) split_sts(bufb + hoff[k], bufb + loff[k], rg[hf][k]);
            __syncthreads();
            int nxt = i + hf + 2;
            if (nxt < GCH) {
                const float* xc = xb + nxt * 64;
                #pragma unroll
                for (int k = 0; k < 4; k++)
                    rg[hf][k] = *(const float4*)(xc + (size_t)(r0 + 16 * k) * NPIX + 4 * px4);
            }
            #pragma unroll
            for (int ks = 0; ks < 4; ks++) {
                uint32_t ac = (aCol + ks * 32) ^ xorv;
                uint32_t bc = (bCol + ks * 32) ^ xorv;
                uint32_t a[2][4], bb[2][4];
                #pragma unroll
                for (int t2 = 0; t2 < 2; t2++)
                    ldsm4(a[t2][0], a[t2][1], a[t2][2], a[t2][3], bufb + aRow[t2] + ac);
                #pragma unroll
                for (int t2 = 0; t2 < 2; t2++)
                    ldsm4(bb[t2][0], bb[t2][1], bb[t2][2], bb[t2][3], bufb + bRow[t2] + bc);
                #pragma unroll
                for (int am = 0; am < 2; am++)
                    #pragma unroll
                    for (int bn = 0; bn < 2; bn++) {
                        mma16816(acc[am][bn][0], a[am][0], a[am][1], a[am][2], a[am][3], bb[bn][0], bb[bn][1]);
                        mma16816(acc[am][bn][1], a[am][0], a[am][1], a[am][2], a[am][3], bb[bn][2], bb[bn][3]);
                    }
            }
        }
    }

    float* P = g_PQ + (size_t)(b * GSPLIT + s) * 8192;
    int lr2 = lane >> 2, lc2 = 2 * (lane & 3);
    #pragma unroll
    for (int am = 0; am < 2; am++)
        #pragma unroll
        for (int bn = 0; bn < 2; bn++)
            #pragma unroll
            for (int q = 0; q < 2; q++) {
                int m = mbase + 16 * am + lr2;
                int d = nbase + 16 * bn + 8 * q + lc2;
                float* a4 = acc[am][bn][q];
                *(float2*)(P + (size_t)m * 64 + d)       = make_float2(a4[0], a4[1]);
                *(float2*)(P + (size_t)(m + 8) * 64 + d) = make_float2(a4[2], a4[3]);
            }
}

// ---------------------------------------------------------------------------
// FUSED: sigma (power iteration) + split-K reduction + A_b = (gamma/sigma)*(G_b W) + I.
// G = hh + lh + lh^T summed over the 8 partials (read directly from g_PQ).
// Writes A image: 64 rows(c) x 256B: [Ah(e) | Al(e)] bf16, row-swizzled.
// grid = NB*2 (h = half of c rows).
__global__ void __launch_bounds__(256) k_matA(const float* __restrict__ W,
                                              const float* __restrict__ gamma,
                                              const float* __restrict__ u) {
    __shared__ float Bs[64][65];
    __shared__ float Ws[64][65];
    __shared__ float vv[64];
    __shared__ float red[64];
    __shared__ float sscale;
    int b = blockIdx.x >> 1, h = blockIdx.x & 1;
    int tid = threadIdx.x;
    const float* P = g_PQ + (size_t)b * GSPLIT * 8192;

    #pragma unroll
    for (int q = 0; q < 4; q++) {
        int f = tid + 256 * q;
        float4 a = ((const float4*)(P + 4096))[f];
        #pragma unroll
        for (int s2 = 1; s2 < GSPLIT; s2++) {
            float4 t2 = ((const float4*)(P + (size_t)s2 * 8192 + 4096))[f];
            a.x += t2.x; a.y += t2.y; a.z += t2.z; a.w += t2.w;
        }
        int row = f >> 4, col = (f & 15) * 4;
        Bs[row][col] = a.x; Bs[row][col + 1] = a.y; Bs[row][col + 2] = a.z; Bs[row][col + 3] = a.w;
        float4 wv = ((const float4*)W)[f];
        Ws[row][col] = wv.x; Ws[row][col + 1] = wv.y; Ws[row][col + 2] = wv.z; Ws[row][col + 3] = wv.w;
    }
    __syncthreads();

    // ---- sigma: v = l2norm(W^T u); sigma = ||W v|| ----
    if (tid < 64) {
        float s = 0.f;
        for (int c = 0; c < 64; c++) s = fmaf(Ws[c][tid], u[c], s);
        vv[tid] = s;
        red[tid] = s * s;
    }
    __syncthreads();
    for (int off = 32; off > 0; off >>= 1) {
        if (tid < off) red[tid] += red[tid + off];
        __syncthreads();
    }
    float nv = fmaxf(sqrtf(red[0]), 1e-12f);
    __syncthreads();
    if (tid < 64) {
        float s = 0.f;
        for (int c = 0; c < 64; c++) s = fmaf(Ws[tid][c], vv[c], s);
        s /= nv;
        red[tid] = s * s;
    }
    __syncthreads();
    for (int off = 32; off > 0; off >>= 1) {
        if (tid < off) red[tid] += red[tid + off];
        __syncthreads();
    }
    if (tid == 0) sscale = gamma[0] / fmaxf(sqrtf(red[0]), 1e-12f);

    // ---- G rows for this CTA's 32 c's: hh (summed from gmem) + lh + lh^T ----
    int c  = 32 * h + (tid >> 3);
    int e0 = (tid & 7) * 8;
    float g[8];
    {
        float4 A0 = ((const float4*)(P + c * 64 + e0))[0];
        float4 A1 = ((const float4*)(P + c * 64 + e0))[1];
        #pragma unroll
        for (int s2 = 1; s2 < GSPLIT; s2++) {
            float4 t0 = ((const float4*)(P + (size_t)s2 * 8192 + c * 64 + e0))[0];
            float4 t1 = ((const float4*)(P + (size_t)s2 * 8192 + c * 64 + e0))[1];
            A0.x += t0.x; A0.y += t0.y; A0.z += t0.z; A0.w += t0.w;
            A1.x += t1.x; A1.y += t1.y; A1.z += t1.z; A1.w += t1.w;
        }
        g[0] = A0.x; g[1] = A0.y; g[2] = A0.z; g[3] = A0.w;
        g[4] = A1.x; g[5] = A1.y; g[6] = A1.z; g[7] = A1.w;
        #pragma unroll
        for (int j = 0; j < 8; j++) g[j] += Bs[c][e0 + j] + Bs[e0 + j][c];
    }
    __syncthreads();
    #pragma unroll
    for (int j = 0; j < 8; j++) Bs[c][e0 + j] = g[j];
    __syncthreads();

    // ---- A = sc*(G W) + I, bf16 hi/lo split, swizzled image ----
    float acc[8] = {};
    #pragma unroll 8
    for (int d = 0; d < 64; d++) {
        float a = Bs[c][d];
        #pragma unroll
        for (int j = 0; j < 8; j++) acc[j] = fmaf(a, Ws[d][e0 + j], acc[j]);
    }
    float sc = sscale;
    uint32_t hw[4], lw[4];
    #pragma unroll
    for (int j = 0; j < 4; j++) {
        float v0 = fmaf(sc, acc[2 * j],     (c == e0 + 2 * j)     ? 1.f : 0.f);
        float v1 = fmaf(sc, acc[2 * j + 1], (c == e0 + 2 * j + 1) ? 1.f : 0.f);
        __nv_bfloat16 h0 = __float2bfloat16(v0), h1 = __float2bfloat16(v1);
        float l0 = v0 - __bfloat162float(h0), l1 = v1 - __bfloat162float(h1);
        __nv_bfloat16 g0 = __float2bfloat16(l0), g1 = __float2bfloat16(l1);
        hw[j] = (uint32_t)__bfloat16_as_ushort(h0) | ((uint32_t)__bfloat16_as_ushort(h1) << 16);
        lw[j] = (uint32_t)__bfloat16_as_ushort(g0) | ((uint32_t)__bfloat16_as_ushort(g1) << 16);
    }
    unsigned char* Ai = g_Aimg + (size_t)b * 16384;
    *(uint4*)(Ai + offr(c, e0 * 2, 256))       = make_uint4(hw[0], hw[1], hw[2], hw[3]);
    *(uint4*)(Ai + offr(c, 128 + e0 * 2, 256)) = make_uint4(lw[0], lw[1], lw[2], lw[3]);
}

// ---------------------------------------------------------------------------
// out tile (128 px): warp tile M=64 (all c), N=16 (px 16*w..16*w+15).
// Quarter-products kept: Ah*xh, Al*xh (j 0..7 @ p=0), Ah*xl (j 0..3 @ p=1).
// Al*xl (~2^-32 relative) dropped: 25% fewer mma/ldsm.
__global__ void __launch_bounds__(256, 3) k_out(const float* __restrict__ x,
                                                float* __restrict__ out) {
    __shared__ __align__(128) unsigned char As[16384];   // 64 rows x 256B
    __shared__ __align__(128) unsigned char Bsi[32768];  // 128 rows ([xh;xl]) x 256B
    int b = blockIdx.y, n0 = blockIdx.x * 128;
    int tid = threadIdx.x;
    int w = tid >> 5, lane = tid & 31;
    int lr = lane & 7, grp = lane >> 3;
    uint32_t asb = smem_u32(As), bsb = smem_u32(Bsi);

    const uint4* Ag = (const uint4*)(g_Aimg + (size_t)b * 16384);
    #pragma unroll
    for (int q = 0; q < 4; q++) ((uint4*)As)[tid + 256 * q] = Ag[tid + 256 * q];

    const float* xb = x + (size_t)b * NC * NPIX + n0;
    int r0 = tid >> 5;
    #pragma unroll
    for (int k = 0; k < 8; k++) {
        int e = r0 + 8 * k;
        float4 v = *(const float4*)(xb + (size_t)e * NPIX + 4 * lane);
        split_sts(bsb + offr(e, lane * 8, 256), bsb + offr(e + 64, lane * 8, 256), v);
    }
    __syncthreads();

    uint32_t xorv = (uint32_t)lr << 4;
    uint32_t aRow[4];
    #pragma unroll
    for (int mt = 0; mt < 4; mt++)
        aRow[mt] = asb + (uint32_t)(16 * mt + lr + 8 * (grp & 1)) * 256;
    uint32_t aColB = (uint32_t)(grp >> 1) * 16;             // + j*32, ^ xorv
    uint32_t bColX = ((uint32_t)(32 * w) + (uint32_t)(grp >> 1) * 16) ^ xorv;
    uint32_t bRowL = (uint32_t)(lr + 8 * (grp & 1));

    float acc[4][2][4] = {};
    #pragma unroll
    for (int j = 0; j < 8; j++) {
        uint32_t ac = (aColB + j * 32) ^ xorv;
        uint32_t a[4][4];
        #pragma unroll
        for (int mt = 0; mt < 4; mt++)
            ldsm4(a[mt][0], a[mt][1], a[mt][2], a[mt][3], aRow[mt] + ac);
        #pragma unroll
        for (int p = 0; p < 2; p++) {
            if (p == 1 && j >= 4) continue;   // skip Al*xl quarter-product
            uint32_t brow = (uint32_t)((j & 3) * 16 + p * 64) + bRowL;
            uint32_t b0, b1, b2, b3;
            ldsm4t(b0, b1, b2, b3, bsb + brow * 256 + bColX);
            #pragma unroll
            for (int mt = 0; mt < 4; mt++) {
                mma16816(acc[mt][0], a[mt][0], a[mt][1], a[mt][2], a[mt][3], b0, b1);
                mma16816(acc[mt][1], a[mt][0], a[mt][1], a[mt][2], a[mt][3], b2, b3);
            }
        }
    }

    float* ob = out + (size_t)b * NC * NPIX + n0;
    int pc = 16 * w + 2 * (lane & 3);
    int lr2 = lane >> 2;
    #pragma unroll
    for (int mt = 0; mt < 4; mt++) {
        int c = 16 * mt + lr2;
        #pragma unroll
        for (int q = 0; q < 2; q++) {
            *(float2*)(ob + (size_t)c * NPIX + pc + 8 * q)       = make_float2(acc[mt][q][0], acc[mt][q][1]);
            *(float2*)(ob + (size_t)(c + 8) * NPIX + pc + 8 * q) = make_float2(acc[mt][q][2], acc[mt][q][3]);
        }
    }
}

// ---------------------------------------------------------------------------
extern "C" void kernel_launch(void* const* d_in, const int* in_sizes, int n_in,
                              void* d_out, int out_size) {
    const float* x     = (const float*)d_in[0];
    const float* W     = (const float*)d_in[1];
    const float* gamma = (const float*)d_in[2];
    const float* u     = (const float*)d_in[3];
    float* out = (float*)d_out;

    k_gram<<<dim3(GSPLIT, NB), 256>>>(x);
    k_matA<<<NB * 2, 256>>>(W, gamma, u);
    k_out<<<dim3(NPIX / 128, NB), 256>>>(x, out);
}